// round 1
// baseline (speedup 1.0000x reference)
#include <cuda_runtime.h>

#define THREADS 128

// One bone step: given parent accumulated rotation Mp (row-major 3x3, row-vector
// convention M_child = M_parent @ R) and parent position pp, euler (ex,ey,ez),
// bone length L -> child M (in-place safe via temp) and child position.
__device__ __forceinline__ void build_R(float ex, float ey, float ez, float* R) {
    float sx, cx, sy, cy, sz, cz;
    __sincosf(ex, &sx, &cx);
    __sincosf(ey, &sy, &cy);
    __sincosf(ez, &sz, &cz);
    // R = Rx @ Ry @ Rz  (matches pytorch3d euler_angles_to_matrix 'XYZ')
    float sxsy = sx * sy;
    float cxsy = cx * sy;
    R[0] = cy * cz;              R[1] = -cy * sz;             R[2] = sy;
    R[3] = fmaf(sxsy, cz,  cx * sz);  R[4] = fmaf(-sxsy, sz, cx * cz);  R[5] = -sx * cy;
    R[6] = fmaf(-cxsy, cz, sx * sz);  R[7] = fmaf(cxsy, sz,  sx * cz);  R[8] = cx * cy;
}

__device__ __forceinline__ void bone_step(float* M, float* p,
                                          float ex, float ey, float ez, float L,
                                          float* po /* smem dst, 3 floats */) {
    float R[9];
    build_R(ex, ey, ez, R);
    float T[9];
#pragma unroll
    for (int r = 0; r < 3; r++) {
#pragma unroll
        for (int c = 0; c < 3; c++) {
            T[3 * r + c] = fmaf(M[3 * r + 0], R[c],
                           fmaf(M[3 * r + 1], R[3 + c],
                                M[3 * r + 2] * R[6 + c]));
        }
    }
#pragma unroll
    for (int i = 0; i < 9; i++) M[i] = T[i];
    p[0] = fmaf(L, M[6], p[0]);
    p[1] = fmaf(L, M[7], p[1]);
    p[2] = fmaf(L, M[8], p[2]);
    po[0] = p[0]; po[1] = p[1]; po[2] = p[2];
}

// Root-attached bone: parent M is identity, parent pos is origin.
__device__ __forceinline__ void root_step(float* M, float* p,
                                          float ex, float ey, float ez, float L,
                                          float* po) {
    build_R(ex, ey, ez, M);
    p[0] = L * M[6];
    p[1] = L * M[7];
    p[2] = L * M[8];
    po[0] = p[0]; po[1] = p[1]; po[2] = p[2];
}

__global__ __launch_bounds__(THREADS)
void fk_kernel(const float* __restrict__ euler,
               const float* __restrict__ blen,
               float* __restrict__ out, int N) {
    __shared__ float s_out[THREADS * 51];

    int n = blockIdx.x * THREADS + threadIdx.x;
    bool active = (n < N);

    if (active) {
        // Load 48 euler floats (192B, 16B-aligned) + 16 bone lengths via float4.
        float e[48];
        float L[16];
        const float4* e4 = reinterpret_cast<const float4*>(euler + (size_t)n * 48);
#pragma unroll
        for (int i = 0; i < 12; i++) {
            float4 v = e4[i];
            e[4 * i + 0] = v.x; e[4 * i + 1] = v.y;
            e[4 * i + 2] = v.z; e[4 * i + 3] = v.w;
        }
        const float4* b4 = reinterpret_cast<const float4*>(blen + (size_t)n * 16);
#pragma unroll
        for (int i = 0; i < 4; i++) {
            float4 v = b4[i];
            L[4 * i + 0] = v.x; L[4 * i + 1] = v.y;
            L[4 * i + 2] = v.z; L[4 * i + 3] = v.w;
        }

        float* po = s_out + threadIdx.x * 51;
        // joint 0 (root) = origin
        po[0] = 0.0f; po[1] = 0.0f; po[2] = 0.0f;

        float M[9], p[3];
        float M8[9], p8[3];

        // chain: 0 -> 1 -> 2 -> 3   (bones 0,1,2)
        root_step(M, p, e[0], e[1], e[2], L[0], po + 3);
        bone_step(M, p, e[3], e[4], e[5], L[1], po + 6);
        bone_step(M, p, e[6], e[7], e[8], L[2], po + 9);

        // chain: 0 -> 4 -> 5 -> 6   (bones 3,4,5)
        root_step(M, p, e[9],  e[10], e[11], L[3], po + 12);
        bone_step(M, p, e[12], e[13], e[14], L[4], po + 15);
        bone_step(M, p, e[15], e[16], e[17], L[5], po + 18);

        // chain: 0 -> 7 -> 8        (bones 6,7)
        root_step(M, p, e[18], e[19], e[20], L[6], po + 21);
        bone_step(M, p, e[21], e[22], e[23], L[7], po + 24);
#pragma unroll
        for (int i = 0; i < 9; i++) M8[i] = M[i];
        p8[0] = p[0]; p8[1] = p[1]; p8[2] = p[2];

        // 8 -> 9 -> 10              (bones 8,9)
        bone_step(M, p, e[24], e[25], e[26], L[8], po + 27);
        bone_step(M, p, e[27], e[28], e[29], L[9], po + 30);

        // 8 -> 11 -> 12 -> 13       (bones 10,11,12)
#pragma unroll
        for (int i = 0; i < 9; i++) M[i] = M8[i];
        p[0] = p8[0]; p[1] = p8[1]; p[2] = p8[2];
        bone_step(M, p, e[30], e[31], e[32], L[10], po + 33);
        bone_step(M, p, e[33], e[34], e[35], L[11], po + 36);
        bone_step(M, p, e[36], e[37], e[38], L[12], po + 39);

        // 8 -> 14 -> 15 -> 16       (bones 13,14,15)
#pragma unroll
        for (int i = 0; i < 9; i++) M[i] = M8[i];
        p[0] = p8[0]; p[1] = p8[1]; p[2] = p8[2];
        bone_step(M, p, e[39], e[40], e[41], L[13], po + 42);
        bone_step(M, p, e[42], e[43], e[44], L[14], po + 45);
        bone_step(M, p, e[45], e[46], e[47], L[15], po + 48);
    }

    __syncthreads();

    // Coalesced flush: this block's output region is contiguous
    // [blockIdx.x*THREADS*51, ...), and s_out layout matches it exactly.
    int firstN = blockIdx.x * THREADS;
    int cnt = N - firstN;
    if (cnt > THREADS) cnt = THREADS;
    int total = cnt * 51;
    size_t base = (size_t)firstN * 51;
    for (int i = threadIdx.x; i < total; i += THREADS) {
        out[base + i] = s_out[i];
    }
}

extern "C" void kernel_launch(void* const* d_in, const int* in_sizes, int n_in,
                              void* d_out, int out_size) {
    const float* euler = (const float*)d_in[0];  // (N,16,3) f32
    const float* blen  = (const float*)d_in[1];  // (N,16,1) f32
    float* out = (float*)d_out;                  // (N,17,3) f32
    int N = in_sizes[0] / 48;
    int blocks = (N + THREADS - 1) / THREADS;
    fk_kernel<<<blocks, THREADS>>>(euler, blen, out, N);
}

// round 2
// speedup vs baseline: 1.6075x; 1.6075x over previous
#include <cuda_runtime.h>

#define THREADS 128

__device__ __forceinline__ void build_R(float ex, float ey, float ez, float* R) {
    float sx, cx, sy, cy, sz, cz;
    __sincosf(ex, &sx, &cx);
    __sincosf(ey, &sy, &cy);
    __sincosf(ez, &sz, &cz);
    float sxsy = sx * sy;
    float cxsy = cx * sy;
    R[0] = cy * cz;                   R[1] = -cy * sz;                  R[2] = sy;
    R[3] = fmaf(sxsy, cz,  cx * sz);  R[4] = fmaf(-sxsy, sz, cx * cz);  R[5] = -sx * cy;
    R[6] = fmaf(-cxsy, cz, sx * sz);  R[7] = fmaf(cxsy, sz,  sx * cz);  R[8] = cx * cy;
}

// M <- M @ R ; p += L * (third row of new M)
__device__ __forceinline__ void chain_step(float* M, float* p,
                                           float ex, float ey, float ez, float L) {
    float R[9];
    build_R(ex, ey, ez, R);
    float T[9];
#pragma unroll
    for (int r = 0; r < 3; r++) {
#pragma unroll
        for (int c = 0; c < 3; c++) {
            T[3 * r + c] = fmaf(M[3 * r + 0], R[c],
                           fmaf(M[3 * r + 1], R[3 + c],
                                M[3 * r + 2] * R[6 + c]));
        }
    }
#pragma unroll
    for (int i = 0; i < 9; i++) M[i] = T[i];
    p[0] = fmaf(L, M[6], p[0]);
    p[1] = fmaf(L, M[7], p[1]);
    p[2] = fmaf(L, M[8], p[2]);
}

__device__ __forceinline__ void root_step(float* M, float* p,
                                          float ex, float ey, float ez, float L) {
    build_R(ex, ey, ez, M);
    p[0] = L * M[6];
    p[1] = L * M[7];
    p[2] = L * M[8];
}

__global__ __launch_bounds__(THREADS)
void fk_kernel(const float* __restrict__ euler,
               const float* __restrict__ blen,
               float* __restrict__ out, int N) {
    // One buffer, 51 floats per thread. Phase 1: holds euler (48/thread).
    // Phase 2: progressively overwritten with positions (51/thread) — safe
    // because bone i's output lands at offset 3(i+1) and we prefetch bone
    // i+1's euler (at the same offset) into registers first. Each thread
    // touches only its own slot, and 51 is odd -> bank-conflict-free.
    __shared__ float sbuf[THREADS * 51];

    int tid = threadIdx.x;
    int firstN = blockIdx.x * THREADS;
    int cnt = N - firstN;
    if (cnt > THREADS) cnt = THREADS;

    // ---- Stage euler, block-coalesced float4 loads ----
    {
        const float4* e4 = reinterpret_cast<const float4*>(euler) + (size_t)firstN * 12;
        int total4 = cnt * 12;
        for (int i = tid; i < total4; i += THREADS) {
            float4 v = e4[i];
            int s = i / 12;              // sample within block
            int k = (i % 12) * 4;        // float offset within sample
            float* d = sbuf + s * 51 + k;
            d[0] = v.x; d[1] = v.y; d[2] = v.z; d[3] = v.w;
        }
    }
    __syncthreads();

    if (tid < cnt) {
        int n = firstN + tid;
        const float4* l4 = reinterpret_cast<const float4*>(blen) + (size_t)n * 4;
        float* slot = sbuf + tid * 51;

        float ex = slot[0], ey = slot[1], ez = slot[2];
        // joint 0 (root) position = origin; slot[0..2] already consumed
        slot[0] = 0.0f; slot[1] = 0.0f; slot[2] = 0.0f;

        float M[9], p[3], M8[9], p8[3];
        float Lv0, Lv1, Lv2, Lv3;
        float nx, ny, nz;

#define LOADL(q) { float4 v = l4[q]; Lv0 = v.x; Lv1 = v.y; Lv2 = v.z; Lv3 = v.w; }
#define PRE(i)   { nx = slot[3*(i)+3]; ny = slot[3*(i)+4]; nz = slot[3*(i)+5]; }
#define EMIT(i)  { slot[3*(i)+3] = p[0]; slot[3*(i)+4] = p[1]; slot[3*(i)+5] = p[2]; \
                   ex = nx; ey = ny; ez = nz; }

        // chain 0 -> 1 -> 2 -> 3
        LOADL(0);
        PRE(0);  root_step(M, p, ex, ey, ez, Lv0);   EMIT(0);
        PRE(1);  chain_step(M, p, ex, ey, ez, Lv1);  EMIT(1);
        PRE(2);  chain_step(M, p, ex, ey, ez, Lv2);  EMIT(2);
        // chain 0 -> 4 -> 5 -> 6
        PRE(3);  root_step(M, p, ex, ey, ez, Lv3);   EMIT(3);
        LOADL(1);
        PRE(4);  chain_step(M, p, ex, ey, ez, Lv0);  EMIT(4);
        PRE(5);  chain_step(M, p, ex, ey, ez, Lv1);  EMIT(5);
        // chain 0 -> 7 -> 8
        PRE(6);  root_step(M, p, ex, ey, ez, Lv2);   EMIT(6);
        PRE(7);  chain_step(M, p, ex, ey, ez, Lv3);  EMIT(7);
        // save spine joint 8 frame
#pragma unroll
        for (int i = 0; i < 9; i++) M8[i] = M[i];
        p8[0] = p[0]; p8[1] = p[1]; p8[2] = p[2];
        // 8 -> 9 -> 10
        LOADL(2);
        PRE(8);  chain_step(M, p, ex, ey, ez, Lv0);  EMIT(8);
        PRE(9);  chain_step(M, p, ex, ey, ez, Lv1);  EMIT(9);
        // 8 -> 11 -> 12 -> 13
#pragma unroll
        for (int i = 0; i < 9; i++) M[i] = M8[i];
        p[0] = p8[0]; p[1] = p8[1]; p[2] = p8[2];
        PRE(10); chain_step(M, p, ex, ey, ez, Lv2);  EMIT(10);
        PRE(11); chain_step(M, p, ex, ey, ez, Lv3);  EMIT(11);
        LOADL(3);
        PRE(12); chain_step(M, p, ex, ey, ez, Lv0);  EMIT(12);
        // 8 -> 14 -> 15 -> 16
#pragma unroll
        for (int i = 0; i < 9; i++) M[i] = M8[i];
        p[0] = p8[0]; p[1] = p8[1]; p[2] = p8[2];
        PRE(13); chain_step(M, p, ex, ey, ez, Lv1);  EMIT(13);
        PRE(14); chain_step(M, p, ex, ey, ez, Lv2);  EMIT(14);
        // last bone: no prefetch (slot[48..50] holds nothing yet)
        chain_step(M, p, ex, ey, ez, Lv3);
        slot[48] = p[0]; slot[49] = p[1]; slot[50] = p[2];

#undef LOADL
#undef PRE
#undef EMIT
    }

    __syncthreads();

    // ---- Coalesced flush: block's output region is contiguous & matches sbuf ----
    {
        float* outp = out + (size_t)firstN * 51;
        int totf = cnt * 51;
        int tot4 = totf >> 2;
        const float4* s4 = reinterpret_cast<const float4*>(sbuf);
        float4* o4 = reinterpret_cast<float4*>(outp);
        for (int i = tid; i < tot4; i += THREADS) {
            o4[i] = s4[i];
        }
        for (int i = (tot4 << 2) + tid; i < totf; i += THREADS) {
            outp[i] = sbuf[i];
        }
    }
}

extern "C" void kernel_launch(void* const* d_in, const int* in_sizes, int n_in,
                              void* d_out, int out_size) {
    const float* euler = (const float*)d_in[0];  // (N,16,3) f32
    const float* blen  = (const float*)d_in[1];  // (N,16,1) f32
    float* out = (float*)d_out;                  // (N,17,3) f32
    int N = in_sizes[0] / 48;
    int blocks = (N + THREADS - 1) / THREADS;
    fk_kernel<<<blocks, THREADS>>>(euler, blen, out, N);
}

// round 4
// speedup vs baseline: 1.7550x; 1.0917x over previous
#include <cuda_runtime.h>
#include <cstdint>

#define THREADS 128

__device__ __forceinline__ uint32_t smem_u32(const void* p) {
    uint32_t a;
    asm("{ .reg .u64 t; cvta.to.shared.u64 t, %1; cvt.u32.u64 %0, t; }"
        : "=r"(a) : "l"(p));
    return a;
}

__device__ __forceinline__ void build_R(float ex, float ey, float ez, float* R) {
    float sx, cx, sy, cy, sz, cz;
    __sincosf(ex, &sx, &cx);
    __sincosf(ey, &sy, &cy);
    __sincosf(ez, &sz, &cz);
    float sxsy = sx * sy;
    float cxsy = cx * sy;
    R[0] = cy * cz;                   R[1] = -cy * sz;                  R[2] = sy;
    R[3] = fmaf(sxsy, cz,  cx * sz);  R[4] = fmaf(-sxsy, sz, cx * cz);  R[5] = -sx * cy;
    R[6] = fmaf(-cxsy, cz, sx * sz);  R[7] = fmaf(cxsy, sz,  sx * cz);  R[8] = cx * cy;
}

// M <- M @ R ; p += L * (third row of new M)
__device__ __forceinline__ void chain_step(float* M, float* p,
                                           float ex, float ey, float ez, float L) {
    float R[9];
    build_R(ex, ey, ez, R);
    float T[9];
#pragma unroll
    for (int r = 0; r < 3; r++) {
#pragma unroll
        for (int c = 0; c < 3; c++) {
            T[3 * r + c] = fmaf(M[3 * r + 0], R[c],
                           fmaf(M[3 * r + 1], R[3 + c],
                                M[3 * r + 2] * R[6 + c]));
        }
    }
#pragma unroll
    for (int i = 0; i < 9; i++) M[i] = T[i];
    p[0] = fmaf(L, M[6], p[0]);
    p[1] = fmaf(L, M[7], p[1]);
    p[2] = fmaf(L, M[8], p[2]);
}

__device__ __forceinline__ void root_step(float* M, float* p,
                                          float ex, float ey, float ez, float L) {
    build_R(ex, ey, ez, M);
    p[0] = L * M[6];
    p[1] = L * M[7];
    p[2] = L * M[8];
}

__global__ __launch_bounds__(THREADS)
void fk_kernel(const float* __restrict__ euler,
               const float* __restrict__ blen,
               float* __restrict__ out, int N) {
    // One buffer, 51 floats per thread (odd stride -> conflict-free banks).
    // Phase 1: euler staging (48/thread). Phase 2: progressively overwritten
    // with positions (51/thread); bone i's output lands at offset 3(i+1) and
    // bone i+1's euler (same offset) is prefetched to registers first.
    // After phase 2 sbuf IS the block's contiguous output image -> bulk store.
    __shared__ __align__(16) float sbuf[THREADS * 51];

    int tid = threadIdx.x;
    int firstN = blockIdx.x * THREADS;
    int cnt = N - firstN;
    if (cnt > THREADS) cnt = THREADS;

    // ---- Stage euler, block-coalesced float4 loads ----
    {
        const float4* e4 = reinterpret_cast<const float4*>(euler) + (size_t)firstN * 12;
        if (cnt == THREADS) {
#pragma unroll
            for (int j = 0; j < 12; j++) {
                int i = j * THREADS + tid;
                float4 v = e4[i];
                int s = i / 12;
                int k = (i % 12) * 4;
                float* d = sbuf + s * 51 + k;
                d[0] = v.x; d[1] = v.y; d[2] = v.z; d[3] = v.w;
            }
        } else {
            int total4 = cnt * 12;
            for (int i = tid; i < total4; i += THREADS) {
                float4 v = e4[i];
                int s = i / 12;
                int k = (i % 12) * 4;
                float* d = sbuf + s * 51 + k;
                d[0] = v.x; d[1] = v.y; d[2] = v.z; d[3] = v.w;
            }
        }
    }
    __syncthreads();

    if (tid < cnt) {
        int n = firstN + tid;
        const float4* l4 = reinterpret_cast<const float4*>(blen) + (size_t)n * 4;
        float* slot = sbuf + tid * 51;

        float ex = slot[0], ey = slot[1], ez = slot[2];
        slot[0] = 0.0f; slot[1] = 0.0f; slot[2] = 0.0f;  // root position

        float M[9], p[3], M8[9], p8[3];
        float Lv0, Lv1, Lv2, Lv3;       // current bone-length quartet
        float Nx0, Ny0, Nz0, Nw0;       // next quartet (prefetch)
        float nx, ny, nz;

#define PRE(i)   { nx = slot[3*(i)+3]; ny = slot[3*(i)+4]; nz = slot[3*(i)+5]; }
#define EMIT(i)  { slot[3*(i)+3] = p[0]; slot[3*(i)+4] = p[1]; slot[3*(i)+5] = p[2]; \
                   ex = nx; ey = ny; ez = nz; }
#define LPRE(q)  { float4 v = l4[q]; Nx0 = v.x; Ny0 = v.y; Nz0 = v.z; Nw0 = v.w; }
#define LSWAP()  { Lv0 = Nx0; Lv1 = Ny0; Lv2 = Nz0; Lv3 = Nw0; }

        LPRE(0); LSWAP();               // quartet 0 now, start fetching quartet 1
        LPRE(1);

        // chain 0 -> 1 -> 2 -> 3
        PRE(0);  root_step(M, p, ex, ey, ez, Lv0);   EMIT(0);
        PRE(1);  chain_step(M, p, ex, ey, ez, Lv1);  EMIT(1);
        PRE(2);  chain_step(M, p, ex, ey, ez, Lv2);  EMIT(2);
        // chain 0 -> 4 -> 5 -> 6
        PRE(3);  root_step(M, p, ex, ey, ez, Lv3);   EMIT(3);
        LSWAP(); LPRE(2);
        PRE(4);  chain_step(M, p, ex, ey, ez, Lv0);  EMIT(4);
        PRE(5);  chain_step(M, p, ex, ey, ez, Lv1);  EMIT(5);
        // chain 0 -> 7 -> 8
        PRE(6);  root_step(M, p, ex, ey, ez, Lv2);   EMIT(6);
        PRE(7);  chain_step(M, p, ex, ey, ez, Lv3);  EMIT(7);
#pragma unroll
        for (int i = 0; i < 9; i++) M8[i] = M[i];
        p8[0] = p[0]; p8[1] = p[1]; p8[2] = p[2];
        // 8 -> 9 -> 10
        LSWAP(); LPRE(3);
        PRE(8);  chain_step(M, p, ex, ey, ez, Lv0);  EMIT(8);
        PRE(9);  chain_step(M, p, ex, ey, ez, Lv1);  EMIT(9);
        // 8 -> 11 -> 12 -> 13
#pragma unroll
        for (int i = 0; i < 9; i++) M[i] = M8[i];
        p[0] = p8[0]; p[1] = p8[1]; p[2] = p8[2];
        PRE(10); chain_step(M, p, ex, ey, ez, Lv2);  EMIT(10);
        PRE(11); chain_step(M, p, ex, ey, ez, Lv3);  EMIT(11);
        LSWAP();
        PRE(12); chain_step(M, p, ex, ey, ez, Lv0);  EMIT(12);
        // 8 -> 14 -> 15 -> 16
#pragma unroll
        for (int i = 0; i < 9; i++) M[i] = M8[i];
        p[0] = p8[0]; p[1] = p8[1]; p[2] = p8[2];
        PRE(13); chain_step(M, p, ex, ey, ez, Lv1);  EMIT(13);
        PRE(14); chain_step(M, p, ex, ey, ez, Lv2);  EMIT(14);
        chain_step(M, p, ex, ey, ez, Lv3);
        slot[48] = p[0]; slot[49] = p[1]; slot[50] = p[2];

#undef PRE
#undef EMIT
#undef LPRE
#undef LSWAP
    }

    __syncthreads();

    // ---- Output: one async bulk store of the block's contiguous image ----
    int bytes = cnt * 51 * 4;
    if ((bytes & 15) == 0) {
        if (tid == 0 && bytes > 0) {
            asm volatile("fence.proxy.async.shared::cta;" ::: "memory");
            float* gdst = out + (size_t)firstN * 51;
            uint32_t ssrc = smem_u32(sbuf);
            asm volatile(
                "cp.async.bulk.global.shared::cta.bulk_group [%0], [%1], %2;"
                :: "l"(gdst), "r"(ssrc), "r"(bytes) : "memory");
            asm volatile("cp.async.bulk.commit_group;" ::: "memory");
            asm volatile("cp.async.bulk.wait_group 0;" ::: "memory");
        }
    } else {
        // Fallback (never hit for N % 4 == 0, kept for generality)
        float* outp = out + (size_t)firstN * 51;
        int totf = cnt * 51;
        for (int i = tid; i < totf; i += THREADS) outp[i] = sbuf[i];
    }
}

extern "C" void kernel_launch(void* const* d_in, const int* in_sizes, int n_in,
                              void* d_out, int out_size) {
    const float* euler = (const float*)d_in[0];  // (N,16,3) f32
    const float* blen  = (const float*)d_in[1];  // (N,16,1) f32
    float* out = (float*)d_out;                  // (N,17,3) f32
    int N = in_sizes[0] / 48;
    int blocks = (N + THREADS - 1) / THREADS;
    fk_kernel<<<blocks, THREADS>>>(euler, blen, out, N);
}